// round 14
// baseline (speedup 1.0000x reference)
#include <cuda_runtime.h>
#include <cuda_fp16.h>
#include <cstdint>

#define NTOK 65536
#define DIM  64
#define KC   4096
#define NKS  4            // 64 / 16 k-steps
#define TM   128          // CTA token tile
#define TN   128          // code tile
#define NT   (KC / TN)    // 32
#define MARGIN 0.2f
#define KSPLIT 32
#define KPER (KC / KSPLIT)   // 128

// output layout: quantized_st [N*D], loss, perplexity, new_e [D*K], new_cs [K], new_un [D*K]
#define OFF_LOSS 4194304
#define OFF_PERP 4194305
#define OFF_NE   4194306
#define OFF_NCS  4456450
#define OFF_NUN  4460546

typedef unsigned long long ull;

// ---------------- device scratch ----------------
__device__ __half g_ahf[NTOK * DIM];   // 8 MB  fp16 x
__device__ __half g_bhf[KC * DIM];     // 0.5MB fp16 (-2e)
__device__ float g_xx[NTOK];           // ||x||^2 per token
__device__ float g_eT[KC * DIM];
__device__ float g_ee[KC];
__device__ int   g_idx[NTOK];
__device__ int   g_amb[NTOK];
__device__ int   g_ambcnt;
__device__ float g_pval[NTOK * KSPLIT];
__device__ int   g_pidx[NTOK * KSPLIT];
__device__ float g_counts[KC];
__device__ float g_sums[KC * DIM];
__device__ float g_scal[3];            // [0]=n_sum, [1]=entropy_sum, [2]=loss_sum

// ---------------- helpers ----------------
__device__ __forceinline__ uint32_t smem_u32(const void* p) {
    uint32_t a;
    asm("{ .reg .u64 t; cvta.to.shared.u64 t, %1; cvt.u32.u64 %0, t; }" : "=r"(a) : "l"(p));
    return a;
}
__device__ __forceinline__ void ldm4(uint32_t* r, uint32_t addr) {
    asm volatile("ldmatrix.sync.aligned.m8n8.x4.shared.b16 {%0,%1,%2,%3}, [%4];"
        : "=r"(r[0]), "=r"(r[1]), "=r"(r[2]), "=r"(r[3]) : "r"(addr));
}
__device__ __forceinline__ void mma_acc(float* c, const uint32_t* a, const uint32_t* b) {
    asm volatile("mma.sync.aligned.m16n8k16.row.col.f32.f16.f16.f32 "
        "{%0,%1,%2,%3}, {%4,%5,%6,%7}, {%8,%9}, {%0,%1,%2,%3};"
        : "+f"(c[0]), "+f"(c[1]), "+f"(c[2]), "+f"(c[3])
        : "r"(a[0]), "r"(a[1]), "r"(a[2]), "r"(a[3]), "r"(b[0]), "r"(b[1]));
}
__device__ __forceinline__ void mma_zero(float* c, const uint32_t* a, const uint32_t* b) {
    asm volatile("mma.sync.aligned.m16n8k16.row.col.f32.f16.f16.f32 "
        "{%0,%1,%2,%3}, {%4,%5,%6,%7}, {%8,%9}, {%10,%10,%10,%10};"
        : "=f"(c[0]), "=f"(c[1]), "=f"(c[2]), "=f"(c[3])
        : "r"(a[0]), "r"(a[1]), "r"(a[2]), "r"(a[3]), "r"(b[0]), "r"(b[1]), "f"(0.0f));
}
// f32x2 (cleanup)
__device__ __forceinline__ ull dup2(float v) {
    ull r; asm("mov.b64 %0, {%1, %1};" : "=l"(r) : "f"(v)); return r;
}
__device__ __forceinline__ void fma2(ull &acc, ull a, ull b) {
    asm("fma.rn.f32x2 %0, %1, %2, %0;" : "+l"(acc) : "l"(a), "l"(b));
}
__device__ __forceinline__ float2 unpack2(ull v) {
    float lo, hi; asm("mov.b64 {%0, %1}, %2;" : "=f"(lo), "=f"(hi) : "l"(v));
    return make_float2(lo, hi);
}

// coarse smem layout: rows padded to 144B; B + ee double-buffered
#define ROWB 144
#define A_OFF  0
#define B_OFF0 18432
#define B_OFF1 36864
#define EE_OFF0 55296
#define EE_OFF1 55808
#define XX_OFF 56320
#define RED_OFF 56832
#define SMEM_DYN 59904

// ---------------- prep (fused): x -> fp16 + ||x||^2 ; e -> eT/ee/bhf/zero ------
#define PREPX_BLOCKS (NTOK * 16 / 256)   // 4096
__global__ void prep_kernel(const float* __restrict__ x, const float* __restrict__ e) {
    if (blockIdx.x < PREPX_BLOCKS) {
        int idx = blockIdx.x * 256 + threadIdx.x;   // over NTOK*16 float4
        int tok = idx >> 4;
        int d4  = (idx & 15) << 2;
        float4 v = *reinterpret_cast<const float4*>(&x[tok * DIM + d4]);
        __half2* hp = reinterpret_cast<__half2*>(&g_ahf[tok * DIM + d4]);
        hp[0] = __floats2half2_rn(v.x, v.y);
        hp[1] = __floats2half2_rn(v.z, v.w);
        float s = v.x * v.x + v.y * v.y + v.z * v.z + v.w * v.w;
        #pragma unroll
        for (int off = 8; off; off >>= 1) s += __shfl_xor_sync(0xffffffffu, s, off, 16);
        if ((idx & 15) == 0) g_xx[tok] = s;
    } else {
        int k = (blockIdx.x - PREPX_BLOCKS) * 256 + threadIdx.x;
        float s = 0.f;
        __half* row = &g_bhf[k * DIM];
        #pragma unroll 8
        for (int d = 0; d < DIM; d++) {
            float v = e[d * KC + k];
            g_eT[k * DIM + d] = v;
            g_sums[k * DIM + d] = 0.f;
            s = fmaf(v, v, s);
            row[d] = __float2half_rn(-2.f * v);
        }
        g_ee[k] = s;
        g_counts[k] = 0.f;
        if (k < 3) g_scal[k] = 0.f;
        if (k == 0) g_ambcnt = 0;
    }
}

// ---------------- coarse: fp16 mma.sync distance GEMM + argmin ----------
// best1/best2 tracked as EXACT floats (FMNMX); packed int only carries the index.
__global__ void __launch_bounds__(128) coarse_kernel() {
    extern __shared__ __align__(16) char sm[];
    const uint32_t sb = smem_u32(sm);
    const int tid  = threadIdx.x;
    const int wid  = tid >> 5;
    const int lane = tid & 31;
    const int wm   = wid >> 1;
    const int wn   = wid & 1;
    const int m0   = blockIdx.x * TM;
    int*   red  = reinterpret_cast<int*>(sm + RED_OFF);
    float* xx_s = reinterpret_cast<float*>(sm + XX_OFF);

    // A tile (once)
    #pragma unroll
    for (int i = 0; i < 8; i++) {
        int lin = tid + i * 128;            // 1024 uint4
        int row = lin >> 3;
        int c16 = lin & 7;
        uint4 v = *reinterpret_cast<const uint4*>(&g_ahf[(m0 + row) * DIM + c16 * 8]);
        *reinterpret_cast<uint4*>(sm + A_OFF + row * ROWB + c16 * 16) = v;
    }
    xx_s[tid] = g_xx[m0 + tid];

    // B tile 0 into buffer 0
    #pragma unroll
    for (int i = 0; i < 8; i++) {
        int lin = tid + i * 128;
        int row = lin >> 3;
        int c16 = lin & 7;
        uint4 v = *reinterpret_cast<const uint4*>(&g_bhf[row * DIM + c16 * 8]);
        *reinterpret_cast<uint4*>(sm + B_OFF0 + row * ROWB + c16 * 16) = v;
    }
    reinterpret_cast<float*>(sm + EE_OFF0)[tid] = g_ee[tid];
    __syncthreads();

    float xr[8];
    #pragma unroll
    for (int mf = 0; mf < 4; mf++)
        #pragma unroll
        for (int h = 0; h < 2; h++)
            xr[2 * mf + h] = xx_s[wm * 64 + mf * 16 + (lane >> 2) + h * 8];

    const uint32_t a_base = sb + A_OFF + (wm * 64 + (lane & 15)) * ROWB + (lane & 16);
    const uint32_t b_lane = (wn * 64 + ((lane & 7) + ((lane & 16) >> 1))) * ROWB
                            + ((lane & 8) << 1);

    int   pk1[8];
    float b1[8], b2[8];
    #pragma unroll
    for (int r = 0; r < 8; r++) { pk1[r] = 0x7FFFFFFF; b1[r] = 3.0e38f; b2[r] = 3.0e38f; }

    const int cbl = wn * 64 + (lane & 3) * 2;

    #pragma unroll 1
    for (int nt = 0; nt < NT; nt++) {
        const int buf = nt & 1;
        const uint32_t b_base = sb + (buf ? B_OFF1 : B_OFF0) + b_lane;
        float* ee_s = reinterpret_cast<float*>(sm + (buf ? EE_OFF1 : EE_OFF0));

        if (nt + 1 < NT) {
            char* bdst = sm + ((nt + 1) & 1 ? B_OFF1 : B_OFF0);
            #pragma unroll
            for (int i = 0; i < 8; i++) {
                int lin = tid + i * 128;
                int row = lin >> 3;
                int c16 = lin & 7;
                uint4 v = *reinterpret_cast<const uint4*>(
                    &g_bhf[((nt + 1) * TN + row) * DIM + c16 * 8]);
                *reinterpret_cast<uint4*>(bdst + row * ROWB + c16 * 16) = v;
            }
            reinterpret_cast<float*>(sm + ((nt + 1) & 1 ? EE_OFF1 : EE_OFF0))[tid] =
                g_ee[(nt + 1) * TN + tid];
        }

        float acc[4][8][4];
        #pragma unroll
        for (int ks = 0; ks < NKS; ks++) {
            uint32_t af[4][4], bq[4][4];
            #pragma unroll
            for (int mf = 0; mf < 4; mf++) ldm4(af[mf], a_base + mf * (16 * ROWB) + ks * 32);
            #pragma unroll
            for (int q = 0; q < 4; q++)    ldm4(bq[q], b_base + q * (16 * ROWB) + ks * 32);
            #pragma unroll
            for (int mf = 0; mf < 4; mf++)
                #pragma unroll
                for (int nf = 0; nf < 8; nf++) {
                    const uint32_t* b = &bq[nf >> 1][(nf & 1) * 2];
                    if (ks == 0) mma_zero(acc[mf][nf], af[mf], b);
                    else         mma_acc(acc[mf][nf], af[mf], b);
                }
        }

        const int kb = nt * TN + cbl;
        #pragma unroll
        for (int nf = 0; nf < 8; nf++) {
            float ee0 = ee_s[cbl + nf * 8];
            float ee1 = ee_s[cbl + nf * 8 + 1];
            int k0 = kb + nf * 8, k1 = k0 + 1;
            #pragma unroll
            for (int mf = 0; mf < 4; mf++) {
                #pragma unroll
                for (int h = 0; h < 2; h++) {
                    int r = 2 * mf + h;
                    float v0 = acc[mf][nf][2 * h + 0] + ee0 + xr[r];
                    float v1 = acc[mf][nf][2 * h + 1] + ee1 + xr[r];
                    b2[r] = fminf(b2[r], fmaxf(b1[r], v0));
                    b1[r] = fminf(b1[r], v0);
                    int p0 = (__float_as_int(v0) & 0xFFFFF000) | k0;
                    pk1[r] = min(pk1[r], p0);
                    b2[r] = fminf(b2[r], fmaxf(b1[r], v1));
                    b1[r] = fminf(b1[r], v1);
                    int p1 = (__float_as_int(v1) & 0xFFFFF000) | k1;
                    pk1[r] = min(pk1[r], p1);
                }
            }
        }
        __syncthreads();
    }

    #pragma unroll
    for (int r = 0; r < 8; r++) {
        #pragma unroll
        for (int m = 1; m <= 2; m <<= 1) {
            int   q1  = __shfl_xor_sync(0xffffffffu, pk1[r], m);
            float b1o = __shfl_xor_sync(0xffffffffu, b1[r], m);
            float b2o = __shfl_xor_sync(0xffffffffu, b2[r], m);
            b2[r] = fminf(fminf(b2[r], b2o), fmaxf(b1[r], b1o));
            b1[r] = fminf(b1[r], b1o);
            pk1[r] = min(pk1[r], q1);
        }
    }
    if ((lane & 3) == 0) {
        #pragma unroll
        for (int r = 0; r < 8; r++) {
            int row = wm * 64 + (r >> 1) * 16 + (lane >> 2) + (r & 1) * 8;
            red[row * 6 + wn * 3 + 0] = pk1[r];
            red[row * 6 + wn * 3 + 1] = __float_as_int(b1[r]);
            red[row * 6 + wn * 3 + 2] = __float_as_int(b2[r]);
        }
    }
    __syncthreads();
    {
        int row = tid;
        int   p1a = red[row * 6 + 0];
        float b1a = __int_as_float(red[row * 6 + 1]);
        float b2a = __int_as_float(red[row * 6 + 2]);
        int   p1b = red[row * 6 + 3];
        float b1b = __int_as_float(red[row * 6 + 4]);
        float b2b = __int_as_float(red[row * 6 + 5]);
        int   p1 = min(p1a, p1b);
        float B1 = fminf(b1a, b1b);
        float B2 = fminf(fminf(b2a, b2b), fmaxf(b1a, b1b));
        int tok = m0 + row;
        g_idx[tok] = p1 & 0xFFF;
        if (B2 - B1 < MARGIN) {
            int pos = atomicAdd(&g_ambcnt, 1);
            g_amb[pos] = tok;
        }
    }
}

// ---------------- cleanup: exact fp32 (f32x2) split-K rescan of ambiguous --------
// 4 tokens x 8 codes micro-tile; KPER=128 -> single B tile per item (fine-grained).
#define CBM 64
#define CLEAN_SMEM (16384 + 32768 + 256)   // As + Bs + toks
__global__ __launch_bounds__(256) void cleanup_kernel(const float* __restrict__ x,
                                                      const float* __restrict__ e) {
    extern __shared__ __align__(16) char csm[];
    float* As   = reinterpret_cast<float*>(csm);               // [DIM][CBM]
    float* Bs   = reinterpret_cast<float*>(csm + 16384);       // [DIM][128]
    int*   toks = reinterpret_cast<int*>(csm + 16384 + 32768);
    const int tid = threadIdx.x;
    const int tx  = tid & 15;
    const int ty  = tid >> 4;
    const int spl = blockIdx.y;
    const int kbeg = spl * KPER;
    const int cnt = g_ambcnt;

    for (int chunk = blockIdx.x; chunk * CBM < cnt; chunk += gridDim.x) {
        __syncthreads();
        if (tid < CBM) {
            int it = chunk * CBM + tid;
            toks[tid] = g_amb[it < cnt ? it : 0];
        }
        __syncthreads();
        #pragma unroll
        for (int i = 0; i < 4; i++) {
            int lin = tid + i * 256;
            int r = lin >> 4;
            int c = (lin & 15) << 2;
            float4 v = *reinterpret_cast<const float4*>(&x[toks[r] * DIM + c]);
            As[(c + 0) * CBM + r] = v.x;
            As[(c + 1) * CBM + r] = v.y;
            As[(c + 2) * CBM + r] = v.z;
            As[(c + 3) * CBM + r] = v.w;
        }

        // single k0 block: KPER == 128
        #pragma unroll
        for (int i = 0; i < 8; i++) {
            int lin = tid + i * 256;
            int d = lin >> 5;
            int c = (lin & 31) << 2;
            *reinterpret_cast<float4*>(&Bs[d * 128 + c]) =
                *reinterpret_cast<const float4*>(&e[d * KC + kbeg + c]);
        }
        __syncthreads();

        ull acc[4][4];
        #pragma unroll
        for (int i = 0; i < 4; i++)
            #pragma unroll
            for (int p = 0; p < 4; p++) acc[i][p] = 0ULL;

        #pragma unroll 8
        for (int d = 0; d < DIM; d++) {
            float4 av = *reinterpret_cast<const float4*>(&As[d * CBM + ty * 4]);
            ull a[4];
            a[0] = dup2(av.x); a[1] = dup2(av.y); a[2] = dup2(av.z); a[3] = dup2(av.w);
            ulonglong2 q0 = *reinterpret_cast<const ulonglong2*>(&Bs[d * 128 + tx * 4]);
            ulonglong2 q1 = *reinterpret_cast<const ulonglong2*>(&Bs[d * 128 + 64 + tx * 4]);
            ull bp[4] = {q0.x, q0.y, q1.x, q1.y};
            #pragma unroll
            for (int i = 0; i < 4; i++)
                #pragma unroll
                for (int p = 0; p < 4; p++)
                    fma2(acc[i][p], a[i], bp[p]);
        }

        float best[4] = {3.0e38f, 3.0e38f, 3.0e38f, 3.0e38f};
        int   bidx[4] = {0, 0, 0, 0};
        #pragma unroll
        for (int p = 0; p < 4; p++) {
            int kbase = kbeg + ((p < 2) ? (tx * 4 + p * 2) : (64 + tx * 4 + (p - 2) * 2));
            float2 ee = *reinterpret_cast<const float2*>(&g_ee[kbase]);
            #pragma unroll
            for (int i = 0; i < 4; i++) {
                float2 s = unpack2(acc[i][p]);
                float s0 = fmaf(-2.f, s.x, ee.x);
                float s1 = fmaf(-2.f, s.y, ee.y);
                if (s0 < best[i]) { best[i] = s0; bidx[i] = kbase; }
                if (s1 < best[i]) { best[i] = s1; bidx[i] = kbase + 1; }
            }
        }

        #pragma unroll
        for (int i = 0; i < 4; i++) {
            float v = best[i];
            int   id = bidx[i];
            #pragma unroll
            for (int off = 8; off > 0; off >>= 1) {
                float v2 = __shfl_down_sync(0xffffffffu, v, off, 16);
                int  id2 = __shfl_down_sync(0xffffffffu, id, off, 16);
                if (v2 < v || (v2 == v && id2 < id)) { v = v2; id = id2; }
            }
            if (tx == 0) {
                int tok = toks[ty * 4 + i];
                g_pval[tok * KSPLIT + spl] = v;
                g_pidx[tok * KSPLIT + spl] = id;
            }
        }
    }
}

// ---------------- combine split-K partials for ambiguous tokens ----------------
__global__ void combine_kernel() {
    int cnt = g_ambcnt;
    for (int i = blockIdx.x * 256 + threadIdx.x; i < cnt; i += gridDim.x * 256) {
        int tok = g_amb[i];
        float v = g_pval[tok * KSPLIT];
        int  id = g_pidx[tok * KSPLIT];
        #pragma unroll
        for (int s = 1; s < KSPLIT; s++) {
            float v2 = g_pval[tok * KSPLIT + s];
            int  id2 = g_pidx[tok * KSPLIT + s];
            if (v2 < v) { v = v2; id = id2; }
        }
        g_idx[tok] = id;
    }
}

// ---------------- gather/quantize + loss partial + EMA scatter ----------------
__global__ __launch_bounds__(256) void quant_kernel(const float* __restrict__ x,
                                                    float* __restrict__ out) {
    int t   = threadIdx.x;
    int tok = blockIdx.x * 4 + (t >> 6);
    int d   = t & 63;
    int idx = g_idx[tok];
    float xv = x[tok * DIM + d];
    float q  = g_eT[idx * DIM + d];
    out[tok * DIM + d] = xv + (q - xv);
    float diff = q - xv;
    float l = diff * diff;
    #pragma unroll
    for (int off = 16; off; off >>= 1) l += __shfl_down_sync(0xffffffffu, l, off);
    __shared__ float part[8];
    if ((t & 31) == 0) part[t >> 5] = l;
    if (d == 0) atomicAdd(&g_counts[idx], 1.0f);
    atomicAdd(&g_sums[idx * DIM + d], xv);
    __syncthreads();
    if (t == 0) {
        float s = 0.f;
        #pragma unroll
        for (int w = 0; w < 8; w++) s += part[w];
        atomicAdd(&g_scal[2], s);
    }
}

// ---------------- new_cs + n / entropy reductions ----------------
__global__ __launch_bounds__(256) void newcs_kernel(const float* __restrict__ cs,
                                                    float* __restrict__ out) {
    int t = threadIdx.x;
    int k = blockIdx.x * 256 + t;
    float cnt = g_counts[k];
    float ncs = 0.1f * cnt + 0.9f * cs[k];
    out[OFF_NCS + k] = ncs;
    float avg = cnt * (1.0f / (float)NTOK);
    float ent = avg * logf(avg + 1e-20f);
    #pragma unroll
    for (int off = 16; off; off >>= 1) {
        ncs += __shfl_down_sync(0xffffffffu, ncs, off);
        ent += __shfl_down_sync(0xffffffffu, ent, off);
    }
    __shared__ float p1[8], p2[8];
    if ((t & 31) == 0) { p1[t >> 5] = ncs; p2[t >> 5] = ent; }
    __syncthreads();
    if (t == 0) {
        float s1 = 0.f, s2 = 0.f;
        #pragma unroll
        for (int w = 0; w < 8; w++) { s1 += p1[w]; s2 += p2[w]; }
        atomicAdd(&g_scal[0], s1);
        atomicAdd(&g_scal[1], s2);
    }
}

// ---------------- new_un, new_e, perplexity, loss ----------------
__global__ __launch_bounds__(256) void final_kernel(const float* __restrict__ cs,
                                                    const float* __restrict__ un,
                                                    float* __restrict__ out) {
    int lin = blockIdx.x * 256 + threadIdx.x;
    int d = lin >> 12;
    int k = lin & (KC - 1);
    float nun = 0.1f * g_sums[k * DIM + d] + 0.9f * un[lin];
    out[OFF_NUN + lin] = nun;
    float n   = g_scal[0];
    float ncs = 0.1f * g_counts[k] + 0.9f * cs[k];
    float stable = (ncs + 1e-20f) / (n + 4.096e-17f) * n;
    out[OFF_NE + lin] = nun / stable;
    if (lin == 0) {
        out[OFF_PERP] = expf(-g_scal[1]);
        out[OFF_LOSS] = g_scal[2] * (0.25f / (float)(NTOK * DIM));
    }
}

// ---------------- launch ----------------
extern "C" void kernel_launch(void* const* d_in, const int* in_sizes, int n_in,
                              void* d_out, int out_size) {
    const float* x  = (const float*)d_in[0];   // [N, D]
    const float* e  = (const float*)d_in[1];   // [D, K]
    const float* cs = (const float*)d_in[2];   // [K]
    const float* un = (const float*)d_in[3];   // [D, K]
    float* out = (float*)d_out;

    cudaFuncSetAttribute(coarse_kernel, cudaFuncAttributeMaxDynamicSharedMemorySize, SMEM_DYN);
    cudaFuncSetAttribute(cleanup_kernel, cudaFuncAttributeMaxDynamicSharedMemorySize, CLEAN_SMEM);

    prep_kernel<<<PREPX_BLOCKS + KC / 256, 256>>>(x, e);
    coarse_kernel<<<NTOK / TM, 128, SMEM_DYN>>>();
    cleanup_kernel<<<dim3(24, KSPLIT), 256, CLEAN_SMEM>>>(x, e);
    combine_kernel<<<64, 256>>>();
    quant_kernel<<<NTOK / 4, 256>>>(x, out);
    newcs_kernel<<<KC / 256, 256>>>(cs, out);
    final_kernel<<<DIM * KC / 256, 256>>>(cs, un, out);
}

// round 15
// speedup vs baseline: 1.0171x; 1.0171x over previous
#include <cuda_runtime.h>
#include <cuda_fp16.h>
#include <cstdint>

#define NTOK 65536
#define DIM  64
#define KC   4096
#define NKS  4            // 64 / 16 k-steps
#define TM   128          // CTA token tile
#define TN   128          // code tile
#define NT   (KC / TN)    // 32
#define MARGIN 0.2f
#define KSPLIT 16
#define KPER (KC / KSPLIT)   // 256

// output layout: quantized_st [N*D], loss, perplexity, new_e [D*K], new_cs [K], new_un [D*K]
#define OFF_LOSS 4194304
#define OFF_PERP 4194305
#define OFF_NE   4194306
#define OFF_NCS  4456450
#define OFF_NUN  4460546

typedef unsigned long long ull;

// ---------------- device scratch ----------------
__device__ __half g_ahf[NTOK * DIM];   // 8 MB  fp16 x
__device__ __half g_bhf[KC * DIM];     // 0.5MB fp16 (-2e)
__device__ float g_xx[NTOK];           // ||x||^2 per token
__device__ float g_eT[KC * DIM];
__device__ float g_ee[KC];
__device__ int   g_idx[NTOK];
__device__ int   g_amb[NTOK];
__device__ int   g_ambcnt;
__device__ float g_pval[NTOK * KSPLIT];
__device__ int   g_pidx[NTOK * KSPLIT];
__device__ float g_counts[KC];
__device__ float g_sums[KC * DIM];
__device__ float g_scal[3];            // [0]=n_sum, [1]=entropy_sum, [2]=loss_sum

// ---------------- helpers ----------------
__device__ __forceinline__ uint32_t smem_u32(const void* p) {
    uint32_t a;
    asm("{ .reg .u64 t; cvta.to.shared.u64 t, %1; cvt.u32.u64 %0, t; }" : "=r"(a) : "l"(p));
    return a;
}
__device__ __forceinline__ void ldm4(uint32_t* r, uint32_t addr) {
    asm volatile("ldmatrix.sync.aligned.m8n8.x4.shared.b16 {%0,%1,%2,%3}, [%4];"
        : "=r"(r[0]), "=r"(r[1]), "=r"(r[2]), "=r"(r[3]) : "r"(addr));
}
__device__ __forceinline__ void mma_acc(float* c, const uint32_t* a, const uint32_t* b) {
    asm volatile("mma.sync.aligned.m16n8k16.row.col.f32.f16.f16.f32 "
        "{%0,%1,%2,%3}, {%4,%5,%6,%7}, {%8,%9}, {%0,%1,%2,%3};"
        : "+f"(c[0]), "+f"(c[1]), "+f"(c[2]), "+f"(c[3])
        : "r"(a[0]), "r"(a[1]), "r"(a[2]), "r"(a[3]), "r"(b[0]), "r"(b[1]));
}
__device__ __forceinline__ void mma_zero(float* c, const uint32_t* a, const uint32_t* b) {
    asm volatile("mma.sync.aligned.m16n8k16.row.col.f32.f16.f16.f32 "
        "{%0,%1,%2,%3}, {%4,%5,%6,%7}, {%8,%9}, {%10,%10,%10,%10};"
        : "=f"(c[0]), "=f"(c[1]), "=f"(c[2]), "=f"(c[3])
        : "r"(a[0]), "r"(a[1]), "r"(a[2]), "r"(a[3]), "r"(b[0]), "r"(b[1]), "f"(0.0f));
}
// f32x2 (cleanup)
__device__ __forceinline__ ull dup2(float v) {
    ull r; asm("mov.b64 %0, {%1, %1};" : "=l"(r) : "f"(v)); return r;
}
__device__ __forceinline__ void fma2(ull &acc, ull a, ull b) {
    asm("fma.rn.f32x2 %0, %1, %2, %0;" : "+l"(acc) : "l"(a), "l"(b));
}
__device__ __forceinline__ float2 unpack2(ull v) {
    float lo, hi; asm("mov.b64 {%0, %1}, %2;" : "=f"(lo), "=f"(hi) : "l"(v));
    return make_float2(lo, hi);
}

// coarse smem layout: rows padded to 144B; B + ee double-buffered
#define ROWB 144
#define A_OFF  0
#define B_OFF0 18432
#define B_OFF1 36864
#define EE_OFF0 55296
#define EE_OFF1 55808
#define XX_OFF 56320
#define RED_OFF 56832
#define SMEM_DYN 59904

// ---------------- prep (fused): x -> fp16 + ||x||^2 ; e -> eT/ee/bhf/zero ------
#define PREPX_BLOCKS (NTOK * 16 / 256)   // 4096
__global__ void prep_kernel(const float* __restrict__ x, const float* __restrict__ e) {
    if (blockIdx.x < PREPX_BLOCKS) {
        int idx = blockIdx.x * 256 + threadIdx.x;   // over NTOK*16 float4
        int tok = idx >> 4;
        int d4  = (idx & 15) << 2;
        float4 v = *reinterpret_cast<const float4*>(&x[tok * DIM + d4]);
        __half2* hp = reinterpret_cast<__half2*>(&g_ahf[tok * DIM + d4]);
        hp[0] = __floats2half2_rn(v.x, v.y);
        hp[1] = __floats2half2_rn(v.z, v.w);
        float s = v.x * v.x + v.y * v.y + v.z * v.z + v.w * v.w;
        #pragma unroll
        for (int off = 8; off; off >>= 1) s += __shfl_xor_sync(0xffffffffu, s, off, 16);
        if ((idx & 15) == 0) g_xx[tok] = s;
    } else {
        int k = (blockIdx.x - PREPX_BLOCKS) * 256 + threadIdx.x;
        float s = 0.f;
        __half* row = &g_bhf[k * DIM];
        #pragma unroll 8
        for (int d = 0; d < DIM; d++) {
            float v = e[d * KC + k];
            g_eT[k * DIM + d] = v;
            g_sums[k * DIM + d] = 0.f;
            s = fmaf(v, v, s);
            row[d] = __float2half_rn(-2.f * v);
        }
        g_ee[k] = s;
        g_counts[k] = 0.f;
        if (k < 3) g_scal[k] = 0.f;
        if (k == 0) g_ambcnt = 0;
    }
}

// ---------------- coarse: fp16 mma.sync distance GEMM + argmin ----------
// best1/best2 tracked as EXACT floats (FMNMX); packed int only carries the index.
__global__ void __launch_bounds__(128) coarse_kernel() {
    extern __shared__ __align__(16) char sm[];
    const uint32_t sb = smem_u32(sm);
    const int tid  = threadIdx.x;
    const int wid  = tid >> 5;
    const int lane = tid & 31;
    const int wm   = wid >> 1;
    const int wn   = wid & 1;
    const int m0   = blockIdx.x * TM;
    int*   red  = reinterpret_cast<int*>(sm + RED_OFF);
    float* xx_s = reinterpret_cast<float*>(sm + XX_OFF);

    // A tile (once)
    #pragma unroll
    for (int i = 0; i < 8; i++) {
        int lin = tid + i * 128;            // 1024 uint4
        int row = lin >> 3;
        int c16 = lin & 7;
        uint4 v = *reinterpret_cast<const uint4*>(&g_ahf[(m0 + row) * DIM + c16 * 8]);
        *reinterpret_cast<uint4*>(sm + A_OFF + row * ROWB + c16 * 16) = v;
    }
    xx_s[tid] = g_xx[m0 + tid];

    // B tile 0 into buffer 0
    #pragma unroll
    for (int i = 0; i < 8; i++) {
        int lin = tid + i * 128;
        int row = lin >> 3;
        int c16 = lin & 7;
        uint4 v = *reinterpret_cast<const uint4*>(&g_bhf[row * DIM + c16 * 8]);
        *reinterpret_cast<uint4*>(sm + B_OFF0 + row * ROWB + c16 * 16) = v;
    }
    reinterpret_cast<float*>(sm + EE_OFF0)[tid] = g_ee[tid];
    __syncthreads();

    float xr[8];
    #pragma unroll
    for (int mf = 0; mf < 4; mf++)
        #pragma unroll
        for (int h = 0; h < 2; h++)
            xr[2 * mf + h] = xx_s[wm * 64 + mf * 16 + (lane >> 2) + h * 8];

    const uint32_t a_base = sb + A_OFF + (wm * 64 + (lane & 15)) * ROWB + (lane & 16);
    const uint32_t b_lane = (wn * 64 + ((lane & 7) + ((lane & 16) >> 1))) * ROWB
                            + ((lane & 8) << 1);

    int   pk1[8];
    float b1[8], b2[8];
    #pragma unroll
    for (int r = 0; r < 8; r++) { pk1[r] = 0x7FFFFFFF; b1[r] = 3.0e38f; b2[r] = 3.0e38f; }

    const int cbl = wn * 64 + (lane & 3) * 2;

    #pragma unroll 1
    for (int nt = 0; nt < NT; nt++) {
        const int buf = nt & 1;
        const uint32_t b_base = sb + (buf ? B_OFF1 : B_OFF0) + b_lane;
        float* ee_s = reinterpret_cast<float*>(sm + (buf ? EE_OFF1 : EE_OFF0));

        if (nt + 1 < NT) {
            char* bdst = sm + ((nt + 1) & 1 ? B_OFF1 : B_OFF0);
            #pragma unroll
            for (int i = 0; i < 8; i++) {
                int lin = tid + i * 128;
                int row = lin >> 3;
                int c16 = lin & 7;
                uint4 v = *reinterpret_cast<const uint4*>(
                    &g_bhf[((nt + 1) * TN + row) * DIM + c16 * 8]);
                *reinterpret_cast<uint4*>(bdst + row * ROWB + c16 * 16) = v;
            }
            reinterpret_cast<float*>(sm + ((nt + 1) & 1 ? EE_OFF1 : EE_OFF0))[tid] =
                g_ee[(nt + 1) * TN + tid];
        }

        float acc[4][8][4];
        #pragma unroll
        for (int ks = 0; ks < NKS; ks++) {
            uint32_t af[4][4], bq[4][4];
            #pragma unroll
            for (int mf = 0; mf < 4; mf++) ldm4(af[mf], a_base + mf * (16 * ROWB) + ks * 32);
            #pragma unroll
            for (int q = 0; q < 4; q++)    ldm4(bq[q], b_base + q * (16 * ROWB) + ks * 32);
            #pragma unroll
            for (int mf = 0; mf < 4; mf++)
                #pragma unroll
                for (int nf = 0; nf < 8; nf++) {
                    const uint32_t* b = &bq[nf >> 1][(nf & 1) * 2];
                    if (ks == 0) mma_zero(acc[mf][nf], af[mf], b);
                    else         mma_acc(acc[mf][nf], af[mf], b);
                }
        }

        const int kb = nt * TN + cbl;
        #pragma unroll
        for (int nf = 0; nf < 8; nf++) {
            float ee0 = ee_s[cbl + nf * 8];
            float ee1 = ee_s[cbl + nf * 8 + 1];
            int k0 = kb + nf * 8, k1 = k0 + 1;
            #pragma unroll
            for (int mf = 0; mf < 4; mf++) {
                #pragma unroll
                for (int h = 0; h < 2; h++) {
                    int r = 2 * mf + h;
                    float v0 = acc[mf][nf][2 * h + 0] + ee0 + xr[r];
                    float v1 = acc[mf][nf][2 * h + 1] + ee1 + xr[r];
                    b2[r] = fminf(b2[r], fmaxf(b1[r], v0));
                    b1[r] = fminf(b1[r], v0);
                    int p0 = (__float_as_int(v0) & 0xFFFFF000) | k0;
                    pk1[r] = min(pk1[r], p0);
                    b2[r] = fminf(b2[r], fmaxf(b1[r], v1));
                    b1[r] = fminf(b1[r], v1);
                    int p1 = (__float_as_int(v1) & 0xFFFFF000) | k1;
                    pk1[r] = min(pk1[r], p1);
                }
            }
        }
        __syncthreads();
    }

    #pragma unroll
    for (int r = 0; r < 8; r++) {
        #pragma unroll
        for (int m = 1; m <= 2; m <<= 1) {
            int   q1  = __shfl_xor_sync(0xffffffffu, pk1[r], m);
            float b1o = __shfl_xor_sync(0xffffffffu, b1[r], m);
            float b2o = __shfl_xor_sync(0xffffffffu, b2[r], m);
            b2[r] = fminf(fminf(b2[r], b2o), fmaxf(b1[r], b1o));
            b1[r] = fminf(b1[r], b1o);
            pk1[r] = min(pk1[r], q1);
        }
    }
    if ((lane & 3) == 0) {
        #pragma unroll
        for (int r = 0; r < 8; r++) {
            int row = wm * 64 + (r >> 1) * 16 + (lane >> 2) + (r & 1) * 8;
            red[row * 6 + wn * 3 + 0] = pk1[r];
            red[row * 6 + wn * 3 + 1] = __float_as_int(b1[r]);
            red[row * 6 + wn * 3 + 2] = __float_as_int(b2[r]);
        }
    }
    __syncthreads();
    {
        int row = tid;
        int   p1a = red[row * 6 + 0];
        float b1a = __int_as_float(red[row * 6 + 1]);
        float b2a = __int_as_float(red[row * 6 + 2]);
        int   p1b = red[row * 6 + 3];
        float b1b = __int_as_float(red[row * 6 + 4]);
        float b2b = __int_as_float(red[row * 6 + 5]);
        int   p1 = min(p1a, p1b);
        float B1 = fminf(b1a, b1b);
        float B2 = fminf(fminf(b2a, b2b), fmaxf(b1a, b1b));
        int tok = m0 + row;
        g_idx[tok] = p1 & 0xFFF;
        if (B2 - B1 < MARGIN) {
            int pos = atomicAdd(&g_ambcnt, 1);
            g_amb[pos] = tok;
        }
    }
}

// ---------------- cleanup: exact fp32 (f32x2) split-K rescan of ambiguous --------
// 4 tokens x 8 codes micro-tile (80 regs -> 3 CTAs/SM); KPER=256 (2 B blocks/item).
#define CBM 64
#define CLEAN_SMEM (16384 + 32768 + 256)   // As + Bs + toks
__global__ __launch_bounds__(256) void cleanup_kernel(const float* __restrict__ x,
                                                      const float* __restrict__ e) {
    extern __shared__ __align__(16) char csm[];
    float* As   = reinterpret_cast<float*>(csm);               // [DIM][CBM]
    float* Bs   = reinterpret_cast<float*>(csm + 16384);       // [DIM][128]
    int*   toks = reinterpret_cast<int*>(csm + 16384 + 32768);
    const int tid = threadIdx.x;
    const int tx  = tid & 15;
    const int ty  = tid >> 4;
    const int spl = blockIdx.y;
    const int kbeg = spl * KPER;
    const int cnt = g_ambcnt;

    for (int chunk = blockIdx.x; chunk * CBM < cnt; chunk += gridDim.x) {
        __syncthreads();
        if (tid < CBM) {
            int it = chunk * CBM + tid;
            toks[tid] = g_amb[it < cnt ? it : 0];
        }
        __syncthreads();
        #pragma unroll
        for (int i = 0; i < 4; i++) {
            int lin = tid + i * 256;
            int r = lin >> 4;
            int c = (lin & 15) << 2;
            float4 v = *reinterpret_cast<const float4*>(&x[toks[r] * DIM + c]);
            As[(c + 0) * CBM + r] = v.x;
            As[(c + 1) * CBM + r] = v.y;
            As[(c + 2) * CBM + r] = v.z;
            As[(c + 3) * CBM + r] = v.w;
        }

        float best[4] = {3.0e38f, 3.0e38f, 3.0e38f, 3.0e38f};
        int   bidx[4] = {0, 0, 0, 0};

        for (int k0 = kbeg; k0 < kbeg + KPER; k0 += 128) {
            __syncthreads();
            #pragma unroll
            for (int i = 0; i < 8; i++) {
                int lin = tid + i * 256;
                int d = lin >> 5;
                int c = (lin & 31) << 2;
                *reinterpret_cast<float4*>(&Bs[d * 128 + c]) =
                    *reinterpret_cast<const float4*>(&e[d * KC + k0 + c]);
            }
            __syncthreads();

            ull acc[4][4];
            #pragma unroll
            for (int i = 0; i < 4; i++)
                #pragma unroll
                for (int p = 0; p < 4; p++) acc[i][p] = 0ULL;

            #pragma unroll 8
            for (int d = 0; d < DIM; d++) {
                float4 av = *reinterpret_cast<const float4*>(&As[d * CBM + ty * 4]);
                ull a[4];
                a[0] = dup2(av.x); a[1] = dup2(av.y); a[2] = dup2(av.z); a[3] = dup2(av.w);
                ulonglong2 q0 = *reinterpret_cast<const ulonglong2*>(&Bs[d * 128 + tx * 4]);
                ulonglong2 q1 = *reinterpret_cast<const ulonglong2*>(&Bs[d * 128 + 64 + tx * 4]);
                ull bp[4] = {q0.x, q0.y, q1.x, q1.y};
                #pragma unroll
                for (int i = 0; i < 4; i++)
                    #pragma unroll
                    for (int p = 0; p < 4; p++)
                        fma2(acc[i][p], a[i], bp[p]);
            }

            #pragma unroll
            for (int p = 0; p < 4; p++) {
                int kbase = k0 + ((p < 2) ? (tx * 4 + p * 2) : (64 + tx * 4 + (p - 2) * 2));
                float2 ee = *reinterpret_cast<const float2*>(&g_ee[kbase]);
                #pragma unroll
                for (int i = 0; i < 4; i++) {
                    float2 s = unpack2(acc[i][p]);
                    float s0 = fmaf(-2.f, s.x, ee.x);
                    float s1 = fmaf(-2.f, s.y, ee.y);
                    if (s0 < best[i]) { best[i] = s0; bidx[i] = kbase; }
                    if (s1 < best[i]) { best[i] = s1; bidx[i] = kbase + 1; }
                }
            }
        }

        #pragma unroll
        for (int i = 0; i < 4; i++) {
            float v = best[i];
            int   id = bidx[i];
            #pragma unroll
            for (int off = 8; off > 0; off >>= 1) {
                float v2 = __shfl_down_sync(0xffffffffu, v, off, 16);
                int  id2 = __shfl_down_sync(0xffffffffu, id, off, 16);
                if (v2 < v || (v2 == v && id2 < id)) { v = v2; id = id2; }
            }
            if (tx == 0) {
                int tok = toks[ty * 4 + i];
                g_pval[tok * KSPLIT + spl] = v;
                g_pidx[tok * KSPLIT + spl] = id;
            }
        }
    }
}

// ---------------- combine split-K partials for ambiguous tokens ----------------
__global__ void combine_kernel() {
    int cnt = g_ambcnt;
    for (int i = blockIdx.x * 256 + threadIdx.x; i < cnt; i += gridDim.x * 256) {
        int tok = g_amb[i];
        float v = g_pval[tok * KSPLIT];
        int  id = g_pidx[tok * KSPLIT];
        #pragma unroll
        for (int s = 1; s < KSPLIT; s++) {
            float v2 = g_pval[tok * KSPLIT + s];
            int  id2 = g_pidx[tok * KSPLIT + s];
            if (v2 < v) { v = v2; id = id2; }
        }
        g_idx[tok] = id;
    }
}

// ---------------- gather/quantize + loss partial + EMA scatter ----------------
__global__ __launch_bounds__(256) void quant_kernel(const float* __restrict__ x,
                                                    float* __restrict__ out) {
    int t   = threadIdx.x;
    int tok = blockIdx.x * 4 + (t >> 6);
    int d   = t & 63;
    int idx = g_idx[tok];
    float xv = x[tok * DIM + d];
    float q  = g_eT[idx * DIM + d];
    out[tok * DIM + d] = xv + (q - xv);
    float diff = q - xv;
    float l = diff * diff;
    #pragma unroll
    for (int off = 16; off; off >>= 1) l += __shfl_down_sync(0xffffffffu, l, off);
    __shared__ float part[8];
    if ((t & 31) == 0) part[t >> 5] = l;
    if (d == 0) atomicAdd(&g_counts[idx], 1.0f);
    atomicAdd(&g_sums[idx * DIM + d], xv);
    __syncthreads();
    if (t == 0) {
        float s = 0.f;
        #pragma unroll
        for (int w = 0; w < 8; w++) s += part[w];
        atomicAdd(&g_scal[2], s);
    }
}

// ---------------- new_cs + n / entropy reductions ----------------
__global__ __launch_bounds__(256) void newcs_kernel(const float* __restrict__ cs,
                                                    float* __restrict__ out) {
    int t = threadIdx.x;
    int k = blockIdx.x * 256 + t;
    float cnt = g_counts[k];
    float ncs = 0.1f * cnt + 0.9f * cs[k];
    out[OFF_NCS + k] = ncs;
    float avg = cnt * (1.0f / (float)NTOK);
    float ent = avg * logf(avg + 1e-20f);
    #pragma unroll
    for (int off = 16; off; off >>= 1) {
        ncs += __shfl_down_sync(0xffffffffu, ncs, off);
        ent += __shfl_down_sync(0xffffffffu, ent, off);
    }
    __shared__ float p1[8], p2[8];
    if ((t & 31) == 0) { p1[t >> 5] = ncs; p2[t >> 5] = ent; }
    __syncthreads();
    if (t == 0) {
        float s1 = 0.f, s2 = 0.f;
        #pragma unroll
        for (int w = 0; w < 8; w++) { s1 += p1[w]; s2 += p2[w]; }
        atomicAdd(&g_scal[0], s1);
        atomicAdd(&g_scal[1], s2);
    }
}

// ---------------- new_un, new_e, perplexity, loss ----------------
__global__ __launch_bounds__(256) void final_kernel(const float* __restrict__ cs,
                                                    const float* __restrict__ un,
                                                    float* __restrict__ out) {
    int lin = blockIdx.x * 256 + threadIdx.x;
    int d = lin >> 12;
    int k = lin & (KC - 1);
    float nun = 0.1f * g_sums[k * DIM + d] + 0.9f * un[lin];
    out[OFF_NUN + lin] = nun;
    float n   = g_scal[0];
    float ncs = 0.1f * g_counts[k] + 0.9f * cs[k];
    float stable = (ncs + 1e-20f) / (n + 4.096e-17f) * n;
    out[OFF_NE + lin] = nun / stable;
    if (lin == 0) {
        out[OFF_PERP] = expf(-g_scal[1]);
        out[OFF_LOSS] = g_scal[2] * (0.25f / (float)(NTOK * DIM));
    }
}

// ---------------- launch ----------------
extern "C" void kernel_launch(void* const* d_in, const int* in_sizes, int n_in,
                              void* d_out, int out_size) {
    const float* x  = (const float*)d_in[0];   // [N, D]
    const float* e  = (const float*)d_in[1];   // [D, K]
    const float* cs = (const float*)d_in[2];   // [K]
    const float* un = (const float*)d_in[3];   // [D, K]
    float* out = (float*)d_out;

    cudaFuncSetAttribute(coarse_kernel, cudaFuncAttributeMaxDynamicSharedMemorySize, SMEM_DYN);
    cudaFuncSetAttribute(cleanup_kernel, cudaFuncAttributeMaxDynamicSharedMemorySize, CLEAN_SMEM);

    prep_kernel<<<PREPX_BLOCKS + KC / 256, 256>>>(x, e);
    coarse_kernel<<<NTOK / TM, 128, SMEM_DYN>>>();
    cleanup_kernel<<<dim3(48, KSPLIT), 256, CLEAN_SMEM>>>(x, e);
    combine_kernel<<<128, 256>>>();
    quant_kernel<<<NTOK / 4, 256>>>(x, out);
    newcs_kernel<<<KC / 256, 256>>>(cs, out);
    final_kernel<<<DIM * KC / 256, 256>>>(cs, un, out);
}

// round 16
// speedup vs baseline: 1.1056x; 1.0870x over previous
#include <cuda_runtime.h>
#include <cuda_fp16.h>
#include <cstdint>

#define NTOK 65536
#define DIM  64
#define KC   4096
#define NKS  4            // 64 / 16 k-steps
#define TM   128          // CTA token tile
#define TN   128          // code tile
#define NT   (KC / TN)    // 32
#define MARGIN 0.2f
#define KSPLIT 16
#define KPER (KC / KSPLIT)   // 256

// output layout: quantized_st [N*D], loss, perplexity, new_e [D*K], new_cs [K], new_un [D*K]
#define OFF_LOSS 4194304
#define OFF_PERP 4194305
#define OFF_NE   4194306
#define OFF_NCS  4456450
#define OFF_NUN  4460546

typedef unsigned long long ull;

// ---------------- device scratch ----------------
__device__ __half g_ahf[NTOK * DIM];   // 8 MB  fp16 x
__device__ __half g_bhf[KC * DIM];     // 0.5MB fp16 (-2e)
__device__ float g_xx[NTOK];           // ||x||^2 per token
__device__ float g_eT[KC * DIM];
__device__ float g_ee[KC];
__device__ int   g_idx[NTOK];
__device__ char  g_flag[NTOK];         // 1 = ambiguous, merge partials in quant
__device__ int   g_amb[NTOK];
__device__ int   g_ambcnt;
__device__ float g_pval[NTOK * KSPLIT];
__device__ int   g_pidx[NTOK * KSPLIT];
__device__ float g_counts[KC];
__device__ float g_sums[KC * DIM];
__device__ float g_scal[3];            // [0]=n_sum, [1]=entropy_sum, [2]=loss_sum

// ---------------- helpers ----------------
__device__ __forceinline__ uint32_t smem_u32(const void* p) {
    uint32_t a;
    asm("{ .reg .u64 t; cvta.to.shared.u64 t, %1; cvt.u32.u64 %0, t; }" : "=r"(a) : "l"(p));
    return a;
}
__device__ __forceinline__ void ldm4(uint32_t* r, uint32_t addr) {
    asm volatile("ldmatrix.sync.aligned.m8n8.x4.shared.b16 {%0,%1,%2,%3}, [%4];"
        : "=r"(r[0]), "=r"(r[1]), "=r"(r[2]), "=r"(r[3]) : "r"(addr));
}
__device__ __forceinline__ void mma_acc(float* c, const uint32_t* a, const uint32_t* b) {
    asm volatile("mma.sync.aligned.m16n8k16.row.col.f32.f16.f16.f32 "
        "{%0,%1,%2,%3}, {%4,%5,%6,%7}, {%8,%9}, {%0,%1,%2,%3};"
        : "+f"(c[0]), "+f"(c[1]), "+f"(c[2]), "+f"(c[3])
        : "r"(a[0]), "r"(a[1]), "r"(a[2]), "r"(a[3]), "r"(b[0]), "r"(b[1]));
}
__device__ __forceinline__ void mma_zero(float* c, const uint32_t* a, const uint32_t* b) {
    asm volatile("mma.sync.aligned.m16n8k16.row.col.f32.f16.f16.f32 "
        "{%0,%1,%2,%3}, {%4,%5,%6,%7}, {%8,%9}, {%10,%10,%10,%10};"
        : "=f"(c[0]), "=f"(c[1]), "=f"(c[2]), "=f"(c[3])
        : "r"(a[0]), "r"(a[1]), "r"(a[2]), "r"(a[3]), "r"(b[0]), "r"(b[1]), "f"(0.0f));
}
// f32x2 (cleanup)
__device__ __forceinline__ ull dup2(float v) {
    ull r; asm("mov.b64 %0, {%1, %1};" : "=l"(r) : "f"(v)); return r;
}
__device__ __forceinline__ void fma2(ull &acc, ull a, ull b) {
    asm("fma.rn.f32x2 %0, %1, %2, %0;" : "+l"(acc) : "l"(a), "l"(b));
}
__device__ __forceinline__ float2 unpack2(ull v) {
    float lo, hi; asm("mov.b64 {%0, %1}, %2;" : "=f"(lo), "=f"(hi) : "l"(v));
    return make_float2(lo, hi);
}

// coarse smem layout: rows padded to 144B; B + ee double-buffered
#define ROWB 144
#define A_OFF  0
#define B_OFF0 18432
#define B_OFF1 36864
#define EE_OFF0 55296
#define EE_OFF1 55808
#define XX_OFF 56320
#define RED_OFF 56832
#define SMEM_DYN 59904

// ---------------- prep (fused): x -> fp16 + ||x||^2 ; e -> eT/ee/bhf/zero ------
#define PREPX_BLOCKS (NTOK * 16 / 256)   // 4096
__global__ void prep_kernel(const float* __restrict__ x, const float* __restrict__ e) {
    if (blockIdx.x < PREPX_BLOCKS) {
        int idx = blockIdx.x * 256 + threadIdx.x;   // over NTOK*16 float4
        int tok = idx >> 4;
        int d4  = (idx & 15) << 2;
        float4 v = *reinterpret_cast<const float4*>(&x[tok * DIM + d4]);
        __half2* hp = reinterpret_cast<__half2*>(&g_ahf[tok * DIM + d4]);
        hp[0] = __floats2half2_rn(v.x, v.y);
        hp[1] = __floats2half2_rn(v.z, v.w);
        float s = v.x * v.x + v.y * v.y + v.z * v.z + v.w * v.w;
        #pragma unroll
        for (int off = 8; off; off >>= 1) s += __shfl_xor_sync(0xffffffffu, s, off, 16);
        if ((idx & 15) == 0) g_xx[tok] = s;
    } else {
        int k = (blockIdx.x - PREPX_BLOCKS) * 256 + threadIdx.x;
        float s = 0.f;
        __half* row = &g_bhf[k * DIM];
        #pragma unroll 8
        for (int d = 0; d < DIM; d++) {
            float v = e[d * KC + k];
            g_eT[k * DIM + d] = v;
            g_sums[k * DIM + d] = 0.f;
            s = fmaf(v, v, s);
            row[d] = __float2half_rn(-2.f * v);
        }
        g_ee[k] = s;
        g_counts[k] = 0.f;
        if (k < 3) g_scal[k] = 0.f;
        if (k == 0) g_ambcnt = 0;
    }
}

// ---------------- coarse: fp16 mma.sync distance GEMM + argmin ----------
// best1/best2 tracked as EXACT floats (FMNMX); packed int only carries the index.
__global__ void __launch_bounds__(128) coarse_kernel() {
    extern __shared__ __align__(16) char sm[];
    const uint32_t sb = smem_u32(sm);
    const int tid  = threadIdx.x;
    const int wid  = tid >> 5;
    const int lane = tid & 31;
    const int wm   = wid >> 1;
    const int wn   = wid & 1;
    const int m0   = blockIdx.x * TM;
    int*   red  = reinterpret_cast<int*>(sm + RED_OFF);
    float* xx_s = reinterpret_cast<float*>(sm + XX_OFF);

    // A tile (once)
    #pragma unroll
    for (int i = 0; i < 8; i++) {
        int lin = tid + i * 128;            // 1024 uint4
        int row = lin >> 3;
        int c16 = lin & 7;
        uint4 v = *reinterpret_cast<const uint4*>(&g_ahf[(m0 + row) * DIM + c16 * 8]);
        *reinterpret_cast<uint4*>(sm + A_OFF + row * ROWB + c16 * 16) = v;
    }
    xx_s[tid] = g_xx[m0 + tid];

    // B tile 0 into buffer 0
    #pragma unroll
    for (int i = 0; i < 8; i++) {
        int lin = tid + i * 128;
        int row = lin >> 3;
        int c16 = lin & 7;
        uint4 v = *reinterpret_cast<const uint4*>(&g_bhf[row * DIM + c16 * 8]);
        *reinterpret_cast<uint4*>(sm + B_OFF0 + row * ROWB + c16 * 16) = v;
    }
    reinterpret_cast<float*>(sm + EE_OFF0)[tid] = g_ee[tid];
    __syncthreads();

    float xr[8];
    #pragma unroll
    for (int mf = 0; mf < 4; mf++)
        #pragma unroll
        for (int h = 0; h < 2; h++)
            xr[2 * mf + h] = xx_s[wm * 64 + mf * 16 + (lane >> 2) + h * 8];

    const uint32_t a_base = sb + A_OFF + (wm * 64 + (lane & 15)) * ROWB + (lane & 16);
    const uint32_t b_lane = (wn * 64 + ((lane & 7) + ((lane & 16) >> 1))) * ROWB
                            + ((lane & 8) << 1);

    int   pk1[8];
    float b1[8], b2[8];
    #pragma unroll
    for (int r = 0; r < 8; r++) { pk1[r] = 0x7FFFFFFF; b1[r] = 3.0e38f; b2[r] = 3.0e38f; }

    const int cbl = wn * 64 + (lane & 3) * 2;

    #pragma unroll 1
    for (int nt = 0; nt < NT; nt++) {
        const int buf = nt & 1;
        const uint32_t b_base = sb + (buf ? B_OFF1 : B_OFF0) + b_lane;
        float* ee_s = reinterpret_cast<float*>(sm + (buf ? EE_OFF1 : EE_OFF0));

        if (nt + 1 < NT) {
            char* bdst = sm + ((nt + 1) & 1 ? B_OFF1 : B_OFF0);
            #pragma unroll
            for (int i = 0; i < 8; i++) {
                int lin = tid + i * 128;
                int row = lin >> 3;
                int c16 = lin & 7;
                uint4 v = *reinterpret_cast<const uint4*>(
                    &g_bhf[((nt + 1) * TN + row) * DIM + c16 * 8]);
                *reinterpret_cast<uint4*>(bdst + row * ROWB + c16 * 16) = v;
            }
            reinterpret_cast<float*>(sm + ((nt + 1) & 1 ? EE_OFF1 : EE_OFF0))[tid] =
                g_ee[(nt + 1) * TN + tid];
        }

        float acc[4][8][4];
        #pragma unroll
        for (int ks = 0; ks < NKS; ks++) {
            uint32_t af[4][4], bq[4][4];
            #pragma unroll
            for (int mf = 0; mf < 4; mf++) ldm4(af[mf], a_base + mf * (16 * ROWB) + ks * 32);
            #pragma unroll
            for (int q = 0; q < 4; q++)    ldm4(bq[q], b_base + q * (16 * ROWB) + ks * 32);
            #pragma unroll
            for (int mf = 0; mf < 4; mf++)
                #pragma unroll
                for (int nf = 0; nf < 8; nf++) {
                    const uint32_t* b = &bq[nf >> 1][(nf & 1) * 2];
                    if (ks == 0) mma_zero(acc[mf][nf], af[mf], b);
                    else         mma_acc(acc[mf][nf], af[mf], b);
                }
        }

        const int kb = nt * TN + cbl;
        #pragma unroll
        for (int nf = 0; nf < 8; nf++) {
            float ee0 = ee_s[cbl + nf * 8];
            float ee1 = ee_s[cbl + nf * 8 + 1];
            int k0 = kb + nf * 8, k1 = k0 + 1;
            #pragma unroll
            for (int mf = 0; mf < 4; mf++) {
                #pragma unroll
                for (int h = 0; h < 2; h++) {
                    int r = 2 * mf + h;
                    float v0 = acc[mf][nf][2 * h + 0] + ee0 + xr[r];
                    float v1 = acc[mf][nf][2 * h + 1] + ee1 + xr[r];
                    b2[r] = fminf(b2[r], fmaxf(b1[r], v0));
                    b1[r] = fminf(b1[r], v0);
                    int p0 = (__float_as_int(v0) & 0xFFFFF000) | k0;
                    pk1[r] = min(pk1[r], p0);
                    b2[r] = fminf(b2[r], fmaxf(b1[r], v1));
                    b1[r] = fminf(b1[r], v1);
                    int p1 = (__float_as_int(v1) & 0xFFFFF000) | k1;
                    pk1[r] = min(pk1[r], p1);
                }
            }
        }
        __syncthreads();
    }

    #pragma unroll
    for (int r = 0; r < 8; r++) {
        #pragma unroll
        for (int m = 1; m <= 2; m <<= 1) {
            int   q1  = __shfl_xor_sync(0xffffffffu, pk1[r], m);
            float b1o = __shfl_xor_sync(0xffffffffu, b1[r], m);
            float b2o = __shfl_xor_sync(0xffffffffu, b2[r], m);
            b2[r] = fminf(fminf(b2[r], b2o), fmaxf(b1[r], b1o));
            b1[r] = fminf(b1[r], b1o);
            pk1[r] = min(pk1[r], q1);
        }
    }
    if ((lane & 3) == 0) {
        #pragma unroll
        for (int r = 0; r < 8; r++) {
            int row = wm * 64 + (r >> 1) * 16 + (lane >> 2) + (r & 1) * 8;
            red[row * 6 + wn * 3 + 0] = pk1[r];
            red[row * 6 + wn * 3 + 1] = __float_as_int(b1[r]);
            red[row * 6 + wn * 3 + 2] = __float_as_int(b2[r]);
        }
    }
    __syncthreads();
    {
        int row = tid;
        int   p1a = red[row * 6 + 0];
        float b1a = __int_as_float(red[row * 6 + 1]);
        float b2a = __int_as_float(red[row * 6 + 2]);
        int   p1b = red[row * 6 + 3];
        float b1b = __int_as_float(red[row * 6 + 4]);
        float b2b = __int_as_float(red[row * 6 + 5]);
        int   p1 = min(p1a, p1b);
        float B1 = fminf(b1a, b1b);
        float B2 = fminf(fminf(b2a, b2b), fmaxf(b1a, b1b));
        int tok = m0 + row;
        g_idx[tok] = p1 & 0xFFF;
        bool amb = (B2 - B1 < MARGIN);
        g_flag[tok] = amb ? 1 : 0;
        if (amb) {
            int pos = atomicAdd(&g_ambcnt, 1);
            g_amb[pos] = tok;
        }
    }
}

// ---------------- cleanup: exact fp32 (f32x2) split-K rescan of ambiguous --------
// 8 tokens x 8 codes micro-tile (both split in 4+4 halves, conflict-free LDS).
#define CBM 128
#define CLEAN_SMEM (DIM * CBM * 4 + DIM * 128 * 4 + 512)
__global__ __launch_bounds__(256) void cleanup_kernel(const float* __restrict__ x,
                                                      const float* __restrict__ e) {
    extern __shared__ __align__(16) char csm[];
    float* As   = reinterpret_cast<float*>(csm);                       // [DIM][CBM]
    float* Bs   = reinterpret_cast<float*>(csm + DIM * CBM * 4);       // [DIM][128]
    int*   toks = reinterpret_cast<int*>(csm + DIM * CBM * 4 + DIM * 128 * 4);
    const int tid = threadIdx.x;
    const int tx  = tid & 15;
    const int ty  = tid >> 4;
    const int spl = blockIdx.y;
    const int kbeg = spl * KPER;
    const int cnt = g_ambcnt;

    for (int chunk = blockIdx.x; chunk * CBM < cnt; chunk += gridDim.x) {
        __syncthreads();
        if (tid < CBM) {
            int it = chunk * CBM + tid;
            toks[tid] = g_amb[it < cnt ? it : 0];
        }
        __syncthreads();
        #pragma unroll
        for (int i = 0; i < 8; i++) {
            int lin = tid + i * 256;
            int r = lin >> 4;
            int c = (lin & 15) << 2;
            float4 v = *reinterpret_cast<const float4*>(&x[toks[r] * DIM + c]);
            As[(c + 0) * CBM + r] = v.x;
            As[(c + 1) * CBM + r] = v.y;
            As[(c + 2) * CBM + r] = v.z;
            As[(c + 3) * CBM + r] = v.w;
        }

        float best[8] = {3.0e38f, 3.0e38f, 3.0e38f, 3.0e38f,
                         3.0e38f, 3.0e38f, 3.0e38f, 3.0e38f};
        int   bidx[8] = {0, 0, 0, 0, 0, 0, 0, 0};

        for (int k0 = kbeg; k0 < kbeg + KPER; k0 += 128) {
            __syncthreads();
            #pragma unroll
            for (int i = 0; i < 8; i++) {
                int lin = tid + i * 256;
                int d = lin >> 5;
                int c = (lin & 31) << 2;
                *reinterpret_cast<float4*>(&Bs[d * 128 + c]) =
                    *reinterpret_cast<const float4*>(&e[d * KC + k0 + c]);
            }
            __syncthreads();

            ull acc[8][4];
            #pragma unroll
            for (int i = 0; i < 8; i++)
                #pragma unroll
                for (int p = 0; p < 4; p++) acc[i][p] = 0ULL;

            #pragma unroll 4
            for (int d = 0; d < DIM; d++) {
                float4 av0 = *reinterpret_cast<const float4*>(&As[d * CBM + ty * 4]);
                float4 av1 = *reinterpret_cast<const float4*>(&As[d * CBM + 64 + ty * 4]);
                ull a[8];
                a[0] = dup2(av0.x); a[1] = dup2(av0.y); a[2] = dup2(av0.z); a[3] = dup2(av0.w);
                a[4] = dup2(av1.x); a[5] = dup2(av1.y); a[6] = dup2(av1.z); a[7] = dup2(av1.w);
                ulonglong2 q0 = *reinterpret_cast<const ulonglong2*>(&Bs[d * 128 + tx * 4]);
                ulonglong2 q1 = *reinterpret_cast<const ulonglong2*>(&Bs[d * 128 + 64 + tx * 4]);
                ull bp[4] = {q0.x, q0.y, q1.x, q1.y};
                #pragma unroll
                for (int i = 0; i < 8; i++)
                    #pragma unroll
                    for (int p = 0; p < 4; p++)
                        fma2(acc[i][p], a[i], bp[p]);
            }

            #pragma unroll
            for (int p = 0; p < 4; p++) {
                int kbase = k0 + ((p < 2) ? (tx * 4 + p * 2) : (64 + tx * 4 + (p - 2) * 2));
                float2 ee = *reinterpret_cast<const float2*>(&g_ee[kbase]);
                #pragma unroll
                for (int i = 0; i < 8; i++) {
                    float2 s = unpack2(acc[i][p]);
                    float s0 = fmaf(-2.f, s.x, ee.x);
                    float s1 = fmaf(-2.f, s.y, ee.y);
                    if (s0 < best[i]) { best[i] = s0; bidx[i] = kbase; }
                    if (s1 < best[i]) { best[i] = s1; bidx[i] = kbase + 1; }
                }
            }
        }

        #pragma unroll
        for (int i = 0; i < 8; i++) {
            float v = best[i];
            int   id = bidx[i];
            #pragma unroll
            for (int off = 8; off > 0; off >>= 1) {
                float v2 = __shfl_down_sync(0xffffffffu, v, off, 16);
                int  id2 = __shfl_down_sync(0xffffffffu, id, off, 16);
                if (v2 < v || (v2 == v && id2 < id)) { v = v2; id = id2; }
            }
            if (tx == 0) {
                int tok = toks[(i < 4) ? (ty * 4 + i) : (64 + ty * 4 + (i - 4))];
                g_pval[tok * KSPLIT + spl] = v;
                g_pidx[tok * KSPLIT + spl] = id;
            }
        }
    }
}

// ---------------- gather/quantize + inline split merge + loss + EMA scatter -----
__global__ __launch_bounds__(256) void quant_kernel(const float* __restrict__ x,
                                                    float* __restrict__ out) {
    __shared__ int sidx[4];
    int t   = threadIdx.x;
    int slot = t >> 6;
    int tok = blockIdx.x * 4 + slot;
    int d   = t & 63;
    int lane = t & 31;

    if (g_flag[tok]) {
        // merge KSPLIT=16 partials: every 16-lane segment loads all 16 and reduces
        int s = d & 15;
        float v = g_pval[tok * KSPLIT + s];
        int  id = g_pidx[tok * KSPLIT + s];
        #pragma unroll
        for (int off = 8; off > 0; off >>= 1) {
            float v2 = __shfl_down_sync(0xffffffffu, v, off, 16);
            int  id2 = __shfl_down_sync(0xffffffffu, id, off, 16);
            if (v2 < v || (v2 == v && id2 < id)) { v = v2; id = id2; }
        }
        // broadcast segment-leader result across the warp's two 16-lane segments
        id = __shfl_sync(0xffffffffu, id, lane & 16, 32);
        if ((t & 63) == 0) sidx[slot] = id;
    }
    __syncthreads();
    int idx = g_flag[tok] ? sidx[slot] : g_idx[tok];

    float xv = x[tok * DIM + d];
    float q  = g_eT[idx * DIM + d];
    out[tok * DIM + d] = xv + (q - xv);
    float diff = q - xv;
    float l = diff * diff;
    #pragma unroll
    for (int off = 16; off; off >>= 1) l += __shfl_down_sync(0xffffffffu, l, off);
    __shared__ float part[8];
    if ((t & 31) == 0) part[t >> 5] = l;
    if (d == 0) atomicAdd(&g_counts[idx], 1.0f);
    atomicAdd(&g_sums[idx * DIM + d], xv);
    __syncthreads();
    if (t == 0) {
        float s = 0.f;
        #pragma unroll
        for (int w = 0; w < 8; w++) s += part[w];
        atomicAdd(&g_scal[2], s);
    }
}

// ---------------- new_cs + n / entropy reductions ----------------
__global__ __launch_bounds__(256) void newcs_kernel(const float* __restrict__ cs,
                                                    float* __restrict__ out) {
    int t = threadIdx.x;
    int k = blockIdx.x * 256 + t;
    float cnt = g_counts[k];
    float ncs = 0.1f * cnt + 0.9f * cs[k];
    out[OFF_NCS + k] = ncs;
    float avg = cnt * (1.0f / (float)NTOK);
    float ent = avg * logf(avg + 1e-20f);
    #pragma unroll
    for (int off = 16; off; off >>= 1) {
        ncs += __shfl_down_sync(0xffffffffu, ncs, off);
        ent += __shfl_down_sync(0xffffffffu, ent, off);
    }
    __shared__ float p1[8], p2[8];
    if ((t & 31) == 0) { p1[t >> 5] = ncs; p2[t >> 5] = ent; }
    __syncthreads();
    if (t == 0) {
        float s1 = 0.f, s2 = 0.f;
        #pragma unroll
        for (int w = 0; w < 8; w++) { s1 += p1[w]; s2 += p2[w]; }
        atomicAdd(&g_scal[0], s1);
        atomicAdd(&g_scal[1], s2);
    }
}

// ---------------- new_un, new_e, perplexity, loss ----------------
__global__ __launch_bounds__(256) void final_kernel(const float* __restrict__ cs,
                                                    const float* __restrict__ un,
                                                    float* __restrict__ out) {
    int lin = blockIdx.x * 256 + threadIdx.x;
    int d = lin >> 12;
    int k = lin & (KC - 1);
    float nun = 0.1f * g_sums[k * DIM + d] + 0.9f * un[lin];
    out[OFF_NUN + lin] = nun;
    float n   = g_scal[0];
    float ncs = 0.1f * g_counts[k] + 0.9f * cs[k];
    float stable = (ncs + 1e-20f) / (n + 4.096e-17f) * n;
    out[OFF_NE + lin] = nun / stable;
    if (lin == 0) {
        out[OFF_PERP] = expf(-g_scal[1]);
        out[OFF_LOSS] = g_scal[2] * (0.25f / (float)(NTOK * DIM));
    }
}

// ---------------- launch ----------------
extern "C" void kernel_launch(void* const* d_in, const int* in_sizes, int n_in,
                              void* d_out, int out_size) {
    const float* x  = (const float*)d_in[0];   // [N, D]
    const float* e  = (const float*)d_in[1];   // [D, K]
    const float* cs = (const float*)d_in[2];   // [K]
    const float* un = (const float*)d_in[3];   // [D, K]
    float* out = (float*)d_out;

    cudaFuncSetAttribute(coarse_kernel, cudaFuncAttributeMaxDynamicSharedMemorySize, SMEM_DYN);
    cudaFuncSetAttribute(cleanup_kernel, cudaFuncAttributeMaxDynamicSharedMemorySize, CLEAN_SMEM);

    prep_kernel<<<PREPX_BLOCKS + KC / 256, 256>>>(x, e);
    coarse_kernel<<<NTOK / TM, 128, SMEM_DYN>>>();
    cleanup_kernel<<<dim3(48, KSPLIT), 256, CLEAN_SMEM>>>(x, e);
    quant_kernel<<<NTOK / 4, 256>>>(x, out);
    newcs_kernel<<<KC / 256, 256>>>(cs, out);
    final_kernel<<<DIM * KC / 256, 256>>>(cs, un, out);
}